// round 3
// baseline (speedup 1.0000x reference)
#include <cuda_runtime.h>
#include <math.h>

#define NMAX 10000
#define EMAX 160000
#define ETOT (EMAX + NMAX)
#define NEG_SLOPE 0.2f
#define GAT_EPS 1e-16f

// ---------------- device scratch ----------------
__device__ int      g_deg[NMAX];
__device__ int      g_rowstart[NMAX + 1];
__device__ int      g_ctr[NMAX];
__device__ unsigned g_csr[ETOT];            // src | (maskedBit<<31)
__device__ __align__(16) float g_h1[NMAX * 64];
__device__ __align__(16) float g_as1[NMAX * 8];
__device__ __align__(16) float g_ad1[NMAX * 8];
__device__ __align__(16) float g_h1a[NMAX * 64];   // elu(gat1 out)
__device__ __align__(16) float g_vs[8 * 64];       // W2 @ a_src2[h]
__device__ __align__(16) float g_vd[8 * 64];       // W2 @ a_dst2[h]
__device__ __align__(16) float g_as2[NMAX * 8];
__device__ __align__(16) float g_ad2[NMAX * 8];
__device__ __align__(16) float g_agg[NMAX * 512];  // per-head aggregated h1a
__device__ __align__(16) float g_h2[NMAX * 1024];  // out2 pre-logsoftmax

// ---------------- CSR build ----------------
__global__ void k_init(int N) {
    int i = blockIdx.x * blockDim.x + threadIdx.x;
    if (i < N) g_deg[i] = 1;
}

__global__ void k_count(const int* __restrict__ ei, int E, int N) {
    int i = blockIdx.x * blockDim.x + threadIdx.x;
    if (i < E) {
        int d = ei[E + i];
        if ((unsigned)d < (unsigned)N) atomicAdd(&g_deg[d], 1);
    }
}

__global__ void k_scan(int N) {
    __shared__ int buf[1024];
    __shared__ int carry;
    int tid = threadIdx.x;
    if (tid == 0) carry = 0;
    __syncthreads();
    for (int base = 0; base < N; base += 1024) {
        int i = base + tid;
        int v = (i < N) ? g_deg[i] : 0;
        buf[tid] = v;
        __syncthreads();
        for (int off = 1; off < 1024; off <<= 1) {
            int t = (tid >= off) ? buf[tid - off] : 0;
            __syncthreads();
            buf[tid] += t;
            __syncthreads();
        }
        int c = carry;
        int incl = buf[tid] + c;
        if (i < N) {
            g_rowstart[i] = incl - v;
            g_ctr[i]      = incl - v;
        }
        __syncthreads();
        if (tid == 1023) carry = buf[1023] + c;
        __syncthreads();
    }
    if (tid == 0) g_rowstart[N] = carry;
}

__global__ void k_fill(const int* __restrict__ ei, int E, int N) {
    int i = blockIdx.x * blockDim.x + threadIdx.x;
    if (i < E) {
        int s = ei[i];
        int d = ei[E + i];
        if ((unsigned)s >= (unsigned)N || (unsigned)d >= (unsigned)N) return;
        unsigned ent = (unsigned)s | ((s == d) ? 0x80000000u : 0u);
        int pos = atomicAdd(&g_ctr[d], 1);
        g_csr[pos] = ent;
    } else if (i < E + N) {
        int nd = i - E;
        int pos = atomicAdd(&g_ctr[nd], 1);
        g_csr[pos] = (unsigned)nd;
    }
}

// ---------------- layer 1 ----------------
__global__ void k_gemm1(const float* __restrict__ x, const float* __restrict__ W1, int N) {
    int col  = threadIdx.x & 63;
    int rs   = threadIdx.x >> 6;
    int row0 = blockIdx.x * 16 + rs * 4;
    const float* xp0 = x + (size_t)min(row0 + 0, N - 1) * 128;
    const float* xp1 = x + (size_t)min(row0 + 1, N - 1) * 128;
    const float* xp2 = x + (size_t)min(row0 + 2, N - 1) * 128;
    const float* xp3 = x + (size_t)min(row0 + 3, N - 1) * 128;
    float a0 = 0.f, a1 = 0.f, a2 = 0.f, a3 = 0.f;
    #pragma unroll 4
    for (int k = 0; k < 128; k++) {
        float w = W1[k * 64 + col];
        a0 = fmaf(xp0[k], w, a0);
        a1 = fmaf(xp1[k], w, a1);
        a2 = fmaf(xp2[k], w, a2);
        a3 = fmaf(xp3[k], w, a3);
    }
    if (row0 + 0 < N) g_h1[(size_t)(row0 + 0) * 64 + col] = a0;
    if (row0 + 1 < N) g_h1[(size_t)(row0 + 1) * 64 + col] = a1;
    if (row0 + 2 < N) g_h1[(size_t)(row0 + 2) * 64 + col] = a2;
    if (row0 + 3 < N) g_h1[(size_t)(row0 + 3) * 64 + col] = a3;
}

__global__ void k_attn1(const float* __restrict__ asw, const float* __restrict__ adw, int N) {
    int i = blockIdx.x * blockDim.x + threadIdx.x;
    if (i >= N * 8) return;
    int n = i >> 3, h = i & 7;
    const float* hp = g_h1 + (size_t)n * 64 + h * 8;
    float s = 0.f, d = 0.f;
    #pragma unroll
    for (int c = 0; c < 8; c++) {
        float v = hp[c];
        s = fmaf(v, asw[h * 8 + c], s);
        d = fmaf(v, adw[h * 8 + c], d);
    }
    g_as1[i] = s;
    g_ad1[i] = d;
}

// one warp per node: single-pass 8-head softmax stats + aggregation + bias + ELU
__global__ void k_agg1(const float* __restrict__ b1, int N) {
    int gw = (blockIdx.x * blockDim.x + threadIdx.x) >> 5;
    int lane = threadIdx.x & 31;
    if (gw >= N) return;
    int n = gw;
    int row = g_rowstart[n];
    int deg = g_deg[n];
    int myh = lane >> 2;

    float4 AD0 = *(const float4*)(g_ad1 + n * 8);
    float4 AD1 = *(const float4*)(g_ad1 + n * 8 + 4);
    float ad[8] = {AD0.x, AD0.y, AD0.z, AD0.w, AD1.x, AD1.y, AD1.z, AD1.w};

    float m[8], s[8];
    #pragma unroll
    for (int h = 0; h < 8; h++) { m[h] = -INFINITY; s[h] = 0.f; }

    for (int j = lane; j < deg; j += 32) {
        unsigned ent = g_csr[row + j];
        int src = (int)(ent & 0x7fffffffu);
        float msk = (ent & 0x80000000u) ? 0.f : 1.f;
        float4 A0 = *(const float4*)(g_as1 + src * 8);
        float4 A1 = *(const float4*)(g_as1 + src * 8 + 4);
        float as_[8] = {A0.x, A0.y, A0.z, A0.w, A1.x, A1.y, A1.z, A1.w};
        #pragma unroll
        for (int h = 0; h < 8; h++) {
            float t = as_[h] + ad[h];
            float e = t > 0.f ? t : NEG_SLOPE * t;
            float nm = fmaxf(m[h], e);
            s[h] = s[h] * __expf(m[h] - nm) + msk * __expf(e - nm);
            m[h] = nm;
        }
    }
    float myM = 0.f, myRS = 0.f;
    #pragma unroll
    for (int h = 0; h < 8; h++) {
        float M = m[h];
        #pragma unroll
        for (int o = 16; o > 0; o >>= 1) M = fmaxf(M, __shfl_xor_sync(0xffffffffu, M, o));
        float S = s[h] * __expf(m[h] - M);
        #pragma unroll
        for (int o = 16; o > 0; o >>= 1) S += __shfl_xor_sync(0xffffffffu, S, o);
        if (h == myh) { myM = M; myRS = 1.f / (S + GAT_EPS); }
    }

    int c0 = lane * 2;
    float adh = ad[0];
    #pragma unroll
    for (int h = 1; h < 8; h++) if (h == myh) adh = ad[h];
    float a0 = 0.f, a1 = 0.f;
    for (int j = 0; j < deg; j++) {
        unsigned ent = g_csr[row + j];
        if (ent & 0x80000000u) continue;
        int src = (int)ent;
        float t = g_as1[src * 8 + myh] + adh;
        float e = t > 0.f ? t : NEG_SLOPE * t;
        float w = __expf(e - myM) * myRS;
        float2 v = *(const float2*)(g_h1 + (size_t)src * 64 + c0);
        a0 = fmaf(v.x, w, a0);
        a1 = fmaf(v.y, w, a1);
    }
    float o0 = a0 + b1[c0], o1 = a1 + b1[c0 + 1];
    o0 = o0 > 0.f ? o0 : (__expf(o0) - 1.f);
    o1 = o1 > 0.f ? o1 : (__expf(o1) - 1.f);
    *(float2*)(g_h1a + (size_t)n * 64 + c0) = make_float2(o0, o1);
}

// ---------------- layer 2 ----------------
// vs[h][k] = sum_c W2[k,h*128+c] * a_src2[h,c] ; same for vd
__global__ void k_prep2(const float* __restrict__ W2, const float* __restrict__ asw,
                        const float* __restrict__ adw) {
    int tid = threadIdx.x;           // 512 threads: h = tid>>6, k = tid&63
    int h = tid >> 6, k = tid & 63;
    const float* wrow = W2 + (size_t)k * 1024 + h * 128;
    const float* sa = asw + h * 128;
    const float* da = adw + h * 128;
    float s = 0.f, d = 0.f;
    #pragma unroll 4
    for (int c = 0; c < 128; c++) {
        float w = wrow[c];
        s = fmaf(w, sa[c], s);
        d = fmaf(w, da[c], d);
    }
    g_vs[h * 64 + k] = s;
    g_vd[h * 64 + k] = d;
}

// as2[n,h] = h1a[n]·vs[h] ; ad2[n,h] = h1a[n]·vd[h]
__global__ void k_attn2(int N) {
    __shared__ float svs[512], svd[512];
    int tid = threadIdx.x;
    for (int i = tid; i < 512; i += 256) { svs[i] = g_vs[i]; svd[i] = g_vd[i]; }
    __syncthreads();
    int i = blockIdx.x * 256 + tid;
    if (i >= N * 8) return;
    int n = i >> 3, h = i & 7;
    const float* hp = g_h1a + (size_t)n * 64;
    float s = 0.f, d = 0.f;
    #pragma unroll 8
    for (int k = 0; k < 64; k++) {
        float v = hp[k];
        s = fmaf(v, svs[h * 64 + k], s);
        d = fmaf(v, svd[h * 64 + k], d);
    }
    g_as2[i] = s;
    g_ad2[i] = d;
}

// block (128 thr) per node: softmax stats + per-head weighted aggregation of h1a
__global__ void k_agg2(int N) {
    __shared__ float s_m[8], s_rd[8];
    __shared__ float s_w[32 * 8];
    __shared__ __align__(16) float s_rows[32][64];
    int n = blockIdx.x;
    int tid = threadIdx.x, lane = tid & 31, wid = tid >> 5;
    int row = g_rowstart[n], deg = g_deg[n];
    int h0 = wid * 2, h1 = wid * 2 + 1;
    float ad0 = g_ad2[n * 8 + h0];
    float ad1v = g_ad2[n * 8 + h1];

    // stats: warp wid owns heads 2wid, 2wid+1 (per-lane online, merge at end)
    {
        float m0 = -INFINITY, s0 = 0.f, m1 = -INFINITY, s1 = 0.f;
        for (int j = lane; j < deg; j += 32) {
            unsigned ent = g_csr[row + j];
            int src = (int)(ent & 0x7fffffffu);
            float msk = (ent & 0x80000000u) ? 0.f : 1.f;
            float t0 = g_as2[src * 8 + h0] + ad0;
            float e0 = t0 > 0.f ? t0 : NEG_SLOPE * t0;
            float nm0 = fmaxf(m0, e0);
            s0 = s0 * __expf(m0 - nm0) + msk * __expf(e0 - nm0);
            m0 = nm0;
            float t1 = g_as2[src * 8 + h1] + ad1v;
            float e1 = t1 > 0.f ? t1 : NEG_SLOPE * t1;
            float nm1 = fmaxf(m1, e1);
            s1 = s1 * __expf(m1 - nm1) + msk * __expf(e1 - nm1);
            m1 = nm1;
        }
        float M0 = m0, M1 = m1;
        #pragma unroll
        for (int o = 16; o > 0; o >>= 1) {
            M0 = fmaxf(M0, __shfl_xor_sync(0xffffffffu, M0, o));
            M1 = fmaxf(M1, __shfl_xor_sync(0xffffffffu, M1, o));
        }
        float S0 = s0 * __expf(m0 - M0);
        float S1 = s1 * __expf(m1 - M1);
        #pragma unroll
        for (int o = 16; o > 0; o >>= 1) {
            S0 += __shfl_xor_sync(0xffffffffu, S0, o);
            S1 += __shfl_xor_sync(0xffffffffu, S1, o);
        }
        if (lane == 0) {
            s_m[h0] = M0; s_rd[h0] = 1.f / (S0 + GAT_EPS);
            s_m[h1] = M1; s_rd[h1] = 1.f / (S1 + GAT_EPS);
        }
    }
    __syncthreads();

    int ht = tid >> 4;                 // head owned by this thread
    int ko = (tid & 15) * 4;           // 4 cols within head
    float4 acc = make_float4(0.f, 0.f, 0.f, 0.f);
    float M0h = s_m[h0], R0h = s_rd[h0], M1h = s_m[h1], R1h = s_rd[h1];

    for (int base = 0; base < deg; base += 32) {
        int cnt = min(32, deg - base);
        __syncthreads();   // protect s_w/s_rows from previous chunk
        if (lane < cnt) {
            unsigned ent = g_csr[row + base + lane];
            int src = (int)(ent & 0x7fffffffu);
            float msk = (ent & 0x80000000u) ? 0.f : 1.f;
            float t0 = g_as2[src * 8 + h0] + ad0;
            float e0 = t0 > 0.f ? t0 : NEG_SLOPE * t0;
            s_w[lane * 8 + h0] = msk * __expf(e0 - M0h) * R0h;
            float t1 = g_as2[src * 8 + h1] + ad1v;
            float e1 = t1 > 0.f ? t1 : NEG_SLOPE * t1;
            s_w[lane * 8 + h1] = msk * __expf(e1 - M1h) * R1h;
        }
        for (int i = tid; i < cnt * 16; i += 128) {
            int r = i >> 4, q = i & 15;
            int src = (int)(g_csr[row + base + r] & 0x7fffffffu);
            ((float4*)s_rows[r])[q] = ((const float4*)(g_h1a + (size_t)src * 64))[q];
        }
        __syncthreads();
        for (int j = 0; j < cnt; j++) {
            float w = s_w[j * 8 + ht];
            float4 v = *(const float4*)&s_rows[j][ko];
            acc.x = fmaf(v.x, w, acc.x);
            acc.y = fmaf(v.y, w, acc.y);
            acc.z = fmaf(v.z, w, acc.z);
            acc.w = fmaf(v.w, w, acc.w);
        }
    }
    *(float4*)(g_agg + (size_t)n * 512 + tid * 4) = acc;
}

// out2: per head hg: h2[n, hg*128+c] = agg[n,hg,:]·W2[:,hg*128+c] + b2  (32-node tile)
__global__ void k_out2(const float* __restrict__ W2, const float* __restrict__ b2, int N) {
    __shared__ __align__(16) float As[32][64];
    int tid = threadIdx.x;
    int hg = blockIdx.y;
    int row0 = blockIdx.x * 32;
    for (int i = tid; i < 32 * 16; i += 128) {
        int r = i >> 4, q = i & 15;
        int rr = min(row0 + r, N - 1);
        ((float4*)As[r])[q] = ((const float4*)(g_agg + (size_t)rr * 512 + hg * 64))[q];
    }
    __syncthreads();
    int col = hg * 128 + tid;
    float acc[32];
    #pragma unroll
    for (int r = 0; r < 32; r++) acc[r] = 0.f;
    #pragma unroll 4
    for (int k = 0; k < 64; k++) {
        float w = W2[(size_t)k * 1024 + col];
        #pragma unroll
        for (int r = 0; r < 32; r++) acc[r] = fmaf(As[r][k], w, acc[r]);
    }
    float bb = b2[col];
    #pragma unroll
    for (int r = 0; r < 32; r++) {
        int rr = row0 + r;
        if (rr < N) g_h2[(size_t)rr * 1024 + col] = acc[r] + bb;
    }
}

// log_softmax over 1024 per node
__global__ void k_lsm(float* __restrict__ out, int N) {
    __shared__ float red[256];
    int n = blockIdx.x, tid = threadIdx.x;
    float4 x = *(const float4*)(g_h2 + (size_t)n * 1024 + tid * 4);
    float tm = fmaxf(fmaxf(x.x, x.y), fmaxf(x.z, x.w));
    red[tid] = tm;
    __syncthreads();
    for (int s = 128; s > 0; s >>= 1) {
        if (tid < s) red[tid] = fmaxf(red[tid], red[tid + s]);
        __syncthreads();
    }
    float bmax = red[0];
    __syncthreads();
    float te = __expf(x.x - bmax) + __expf(x.y - bmax) + __expf(x.z - bmax) + __expf(x.w - bmax);
    red[tid] = te;
    __syncthreads();
    for (int s = 128; s > 0; s >>= 1) {
        if (tid < s) red[tid] += red[tid + s];
        __syncthreads();
    }
    float lse = bmax + logf(red[0]);
    float4 o = make_float4(x.x - lse, x.y - lse, x.z - lse, x.w - lse);
    *(float4*)(out + (size_t)n * 1024 + tid * 4) = o;
}

// ---------------- launcher ----------------
extern "C" void kernel_launch(void* const* d_in, const int* in_sizes, int n_in,
                              void* d_out, int out_size) {
    const float* x   = (const float*)d_in[0];
    const int*   ei  = (const int*)d_in[1];
    const float* W1  = (const float*)d_in[2];
    const float* aS1 = (const float*)d_in[3];
    const float* aD1 = (const float*)d_in[4];
    const float* b1  = (const float*)d_in[5];
    const float* W2  = (const float*)d_in[6];
    const float* aS2 = (const float*)d_in[7];
    const float* aD2 = (const float*)d_in[8];
    const float* b2  = (const float*)d_in[9];
    float*       out = (float*)d_out;

    int N = in_sizes[0] / 128;
    int E = in_sizes[1] / 2;

    k_init <<<(N + 255) / 256, 256>>>(N);
    k_count<<<(E + 255) / 256, 256>>>(ei, E, N);
    k_scan <<<1, 1024>>>(N);
    k_fill <<<(E + N + 255) / 256, 256>>>(ei, E, N);

    k_gemm1<<<(N + 15) / 16, 256>>>(x, W1, N);
    k_attn1<<<(N * 8 + 255) / 256, 256>>>(aS1, aD1, N);
    k_agg1 <<<(N * 32 + 255) / 256, 256>>>(b1, N);

    k_prep2<<<1, 512>>>(W2, aS2, aD2);
    k_attn2<<<(N * 8 + 255) / 256, 256>>>(N);
    k_agg2 <<<N, 128>>>(N);
    dim3 g2((N + 31) / 32, 8);
    k_out2 <<<g2, 128>>>(W2, b2, N);
    k_lsm  <<<N, 256>>>(out, N);
}

// round 4
// speedup vs baseline: 1.2490x; 1.2490x over previous
#include <cuda_runtime.h>
#include <math.h>

#define NMAX 10000
#define EMAX 160000
#define ETOT (EMAX + NMAX)
#define NEG_SLOPE 0.2f
#define GAT_EPS 1e-16f

// ---------------- device scratch ----------------
__device__ int      g_deg[NMAX];            // after k_scan: deg incl. self-loop
__device__ int      g_rowstart[NMAX + 1];
__device__ int      g_ctr[NMAX];
__device__ unsigned g_csr[ETOT];            // src | (maskedBit<<31)
__device__ __align__(16) float g_h1[NMAX * 64];
__device__ __align__(16) float g_as1[NMAX * 8];
__device__ __align__(16) float g_ad1[NMAX * 8];
__device__ __align__(16) float g_h1a[NMAX * 64];
__device__ __align__(16) float g_vs[8 * 64];       // W2 @ a_src2[h]
__device__ __align__(16) float g_vd[8 * 64];
__device__ __align__(16) float g_as2[NMAX * 8];
__device__ __align__(16) float g_ad2[NMAX * 8];
__device__ __align__(16) float g_agg[NMAX * 512];
__device__ __align__(16) float g_h2[NMAX * 1024];

// ---------------- CSR build ----------------
__global__ void k_count(const int* __restrict__ ei, int E, int N) {
    int i = blockIdx.x * blockDim.x + threadIdx.x;
    if (i < E) {
        int d = ei[E + i];
        if ((unsigned)d < (unsigned)N) atomicAdd(&g_deg[d], 1);
    }
}

// warp-shuffle scan; also places the appended self-loop first in each row,
// finalizes g_deg (incl. self loop) and initializes g_ctr past the self loop.
__global__ void k_scan(int N) {
    __shared__ int wpre[32];
    __shared__ int carry;
    int tid = threadIdx.x, lane = tid & 31, wid = tid >> 5;
    if (tid == 0) carry = 0;
    __syncthreads();
    for (int base = 0; base < N; base += 1024) {
        int i = base + tid;
        int v = (i < N) ? (g_deg[i] + 1) : 0;
        int inc = v;
        #pragma unroll
        for (int o = 1; o < 32; o <<= 1) {
            int t = __shfl_up_sync(0xffffffffu, inc, o);
            if (lane >= o) inc += t;
        }
        if (lane == 31) wpre[wid] = inc;
        __syncthreads();
        if (wid == 0) {
            int w = wpre[lane];
            int wi = w;
            #pragma unroll
            for (int o = 1; o < 32; o <<= 1) {
                int t = __shfl_up_sync(0xffffffffu, wi, o);
                if (lane >= o) wi += t;
            }
            wpre[lane] = wi - w;   // exclusive prefix over warps
        }
        __syncthreads();
        int excl = carry + wpre[wid] + inc - v;
        if (i < N) {
            g_rowstart[i] = excl;
            g_deg[i] = v;
            g_csr[excl] = (unsigned)i;   // appended self-loop (mask=1)
            g_ctr[i] = excl + 1;
        }
        __syncthreads();
        if (tid == 1023) carry += wpre[31] + inc;
        __syncthreads();
    }
    if (tid == 0) g_rowstart[N] = carry;
}

__global__ void k_fill(const int* __restrict__ ei, int E, int N) {
    int i = blockIdx.x * blockDim.x + threadIdx.x;
    if (i >= E) return;
    int s = ei[i];
    int d = ei[E + i];
    if ((unsigned)s >= (unsigned)N || (unsigned)d >= (unsigned)N) return;
    unsigned ent = (unsigned)s | ((s == d) ? 0x80000000u : 0u);
    int pos = atomicAdd(&g_ctr[d], 1);
    g_csr[pos] = ent;
}

// ---------------- layer 1: GEMM + attn dots fused ----------------
__global__ void k_gemm1f(const float* __restrict__ x, const float* __restrict__ W1,
                         const float* __restrict__ asw, const float* __restrict__ adw, int N) {
    int col  = threadIdx.x & 63;
    int rs   = threadIdx.x >> 6;
    int row0 = blockIdx.x * 16 + rs * 4;
    const float* xp0 = x + (size_t)min(row0 + 0, N - 1) * 128;
    const float* xp1 = x + (size_t)min(row0 + 1, N - 1) * 128;
    const float* xp2 = x + (size_t)min(row0 + 2, N - 1) * 128;
    const float* xp3 = x + (size_t)min(row0 + 3, N - 1) * 128;
    float a[4] = {0.f, 0.f, 0.f, 0.f};
    #pragma unroll 4
    for (int k = 0; k < 128; k++) {
        float w = W1[k * 64 + col];
        a[0] = fmaf(xp0[k], w, a[0]);
        a[1] = fmaf(xp1[k], w, a[1]);
        a[2] = fmaf(xp2[k], w, a[2]);
        a[3] = fmaf(xp3[k], w, a[3]);
    }
    #pragma unroll
    for (int r = 0; r < 4; r++)
        if (row0 + r < N) g_h1[(size_t)(row0 + r) * 64 + col] = a[r];

    // attention dots: head = col>>3, 8-lane segmented reductions
    float ws = asw[col], wd = adw[col];
    #pragma unroll
    for (int r = 0; r < 4; r++) {
        float ps = a[r] * ws, pd = a[r] * wd;
        ps += __shfl_down_sync(0xffffffffu, ps, 4);
        pd += __shfl_down_sync(0xffffffffu, pd, 4);
        ps += __shfl_down_sync(0xffffffffu, ps, 2);
        pd += __shfl_down_sync(0xffffffffu, pd, 2);
        ps += __shfl_down_sync(0xffffffffu, ps, 1);
        pd += __shfl_down_sync(0xffffffffu, pd, 1);
        if ((col & 7) == 0 && row0 + r < N) {
            g_as1[(row0 + r) * 8 + (col >> 3)] = ps;
            g_ad1[(row0 + r) * 8 + (col >> 3)] = pd;
        }
    }
}

// vs[h][k] = sum_c W2[k, h*128+c] * a_src2[h,c]
__global__ void k_prep2(const float* __restrict__ W2, const float* __restrict__ asw,
                        const float* __restrict__ adw) {
    int tid = threadIdx.x;
    int h = tid >> 6, k = tid & 63;
    const float* wrow = W2 + (size_t)k * 1024 + h * 128;
    const float* sa = asw + h * 128;
    const float* da = adw + h * 128;
    float s = 0.f, d = 0.f;
    #pragma unroll 4
    for (int c = 0; c < 128; c++) {
        float w = wrow[c];
        s = fmaf(w, sa[c], s);
        d = fmaf(w, da[c], d);
    }
    g_vs[h * 64 + k] = s;
    g_vd[h * 64 + k] = d;
}

// one warp per node: layer1 softmax+aggregate+bias+ELU, then layer2 attn dots
__global__ void k_agg1f(const float* __restrict__ b1, int N) {
    int gw = (blockIdx.x * blockDim.x + threadIdx.x) >> 5;
    int lane = threadIdx.x & 31;
    if (gw >= N) return;
    int n = gw;
    int row = g_rowstart[n];
    int deg = g_deg[n];
    int myh = lane >> 2;

    float4 AD0 = *(const float4*)(g_ad1 + n * 8);
    float4 AD1 = *(const float4*)(g_ad1 + n * 8 + 4);
    float ad[8] = {AD0.x, AD0.y, AD0.z, AD0.w, AD1.x, AD1.y, AD1.z, AD1.w};

    float m[8], s[8];
    #pragma unroll
    for (int h = 0; h < 8; h++) { m[h] = -INFINITY; s[h] = 0.f; }

    for (int j = lane; j < deg; j += 32) {
        unsigned ent = g_csr[row + j];
        int src = (int)(ent & 0x7fffffffu);
        float msk = (ent & 0x80000000u) ? 0.f : 1.f;
        float4 A0 = *(const float4*)(g_as1 + src * 8);
        float4 A1 = *(const float4*)(g_as1 + src * 8 + 4);
        float as_[8] = {A0.x, A0.y, A0.z, A0.w, A1.x, A1.y, A1.z, A1.w};
        #pragma unroll
        for (int h = 0; h < 8; h++) {
            float t = as_[h] + ad[h];
            float e = t > 0.f ? t : NEG_SLOPE * t;
            float nm = fmaxf(m[h], e);
            s[h] = s[h] * __expf(m[h] - nm) + msk * __expf(e - nm);
            m[h] = nm;
        }
    }
    float myM = 0.f, myRS = 0.f;
    #pragma unroll
    for (int h = 0; h < 8; h++) {
        float M = m[h];
        #pragma unroll
        for (int o = 16; o > 0; o >>= 1) M = fmaxf(M, __shfl_xor_sync(0xffffffffu, M, o));
        float S = s[h] * __expf(m[h] - M);
        #pragma unroll
        for (int o = 16; o > 0; o >>= 1) S += __shfl_xor_sync(0xffffffffu, S, o);
        if (h == myh) { myM = M; myRS = 1.f / (S + GAT_EPS); }
    }

    int c0 = lane * 2;
    float adh = ad[0];
    #pragma unroll
    for (int h = 1; h < 8; h++) if (h == myh) adh = ad[h];
    float a0 = 0.f, a1 = 0.f;
    for (int j = 0; j < deg; j++) {
        unsigned ent = g_csr[row + j];
        if (ent & 0x80000000u) continue;
        int src = (int)ent;
        float t = g_as1[src * 8 + myh] + adh;
        float e = t > 0.f ? t : NEG_SLOPE * t;
        float w = __expf(e - myM) * myRS;
        float2 v = *(const float2*)(g_h1 + (size_t)src * 64 + c0);
        a0 = fmaf(v.x, w, a0);
        a1 = fmaf(v.y, w, a1);
    }
    float o0 = a0 + b1[c0], o1 = a1 + b1[c0 + 1];
    o0 = o0 > 0.f ? o0 : (__expf(o0) - 1.f);
    o1 = o1 > 0.f ? o1 : (__expf(o1) - 1.f);
    *(float2*)(g_h1a + (size_t)n * 64 + c0) = make_float2(o0, o1);

    // fused layer-2 attention dots: as2[n,h] = h1a[n]·vs[h]
    #pragma unroll
    for (int h = 0; h < 8; h++) {
        float ps = o0 * g_vs[h * 64 + c0] + o1 * g_vs[h * 64 + c0 + 1];
        float pd = o0 * g_vd[h * 64 + c0] + o1 * g_vd[h * 64 + c0 + 1];
        #pragma unroll
        for (int o = 16; o > 0; o >>= 1) {
            ps += __shfl_xor_sync(0xffffffffu, ps, o);
            pd += __shfl_xor_sync(0xffffffffu, pd, o);
        }
        if (lane == 0) {
            g_as2[n * 8 + h] = ps;
            g_ad2[n * 8 + h] = pd;
        }
    }
}

// block (128 thr) per node: softmax stats + per-head weighted aggregation of h1a
__global__ void k_agg2(int N) {
    __shared__ float s_m[8], s_rd[8];
    __shared__ float s_w[32 * 8];
    __shared__ __align__(16) float s_rows[32][64];
    int n = blockIdx.x;
    int tid = threadIdx.x, lane = tid & 31, wid = tid >> 5;
    int row = g_rowstart[n], deg = g_deg[n];
    int h0 = wid * 2, h1 = wid * 2 + 1;
    float ad0 = g_ad2[n * 8 + h0];
    float ad1v = g_ad2[n * 8 + h1];

    {
        float m0 = -INFINITY, s0 = 0.f, m1 = -INFINITY, s1 = 0.f;
        for (int j = lane; j < deg; j += 32) {
            unsigned ent = g_csr[row + j];
            int src = (int)(ent & 0x7fffffffu);
            float msk = (ent & 0x80000000u) ? 0.f : 1.f;
            float t0 = g_as2[src * 8 + h0] + ad0;
            float e0 = t0 > 0.f ? t0 : NEG_SLOPE * t0;
            float nm0 = fmaxf(m0, e0);
            s0 = s0 * __expf(m0 - nm0) + msk * __expf(e0 - nm0);
            m0 = nm0;
            float t1 = g_as2[src * 8 + h1] + ad1v;
            float e1 = t1 > 0.f ? t1 : NEG_SLOPE * t1;
            float nm1 = fmaxf(m1, e1);
            s1 = s1 * __expf(m1 - nm1) + msk * __expf(e1 - nm1);
            m1 = nm1;
        }
        float M0 = m0, M1 = m1;
        #pragma unroll
        for (int o = 16; o > 0; o >>= 1) {
            M0 = fmaxf(M0, __shfl_xor_sync(0xffffffffu, M0, o));
            M1 = fmaxf(M1, __shfl_xor_sync(0xffffffffu, M1, o));
        }
        float S0 = s0 * __expf(m0 - M0);
        float S1 = s1 * __expf(m1 - M1);
        #pragma unroll
        for (int o = 16; o > 0; o >>= 1) {
            S0 += __shfl_xor_sync(0xffffffffu, S0, o);
            S1 += __shfl_xor_sync(0xffffffffu, S1, o);
        }
        if (lane == 0) {
            s_m[h0] = M0; s_rd[h0] = 1.f / (S0 + GAT_EPS);
            s_m[h1] = M1; s_rd[h1] = 1.f / (S1 + GAT_EPS);
        }
    }
    __syncthreads();

    int ht = tid >> 4;
    int ko = (tid & 15) * 4;
    float4 acc = make_float4(0.f, 0.f, 0.f, 0.f);
    float M0h = s_m[h0], R0h = s_rd[h0], M1h = s_m[h1], R1h = s_rd[h1];

    for (int base = 0; base < deg; base += 32) {
        int cnt = min(32, deg - base);
        __syncthreads();
        if (lane < cnt) {
            unsigned ent = g_csr[row + base + lane];
            int src = (int)(ent & 0x7fffffffu);
            float msk = (ent & 0x80000000u) ? 0.f : 1.f;
            float t0 = g_as2[src * 8 + h0] + ad0;
            float e0 = t0 > 0.f ? t0 : NEG_SLOPE * t0;
            s_w[lane * 8 + h0] = msk * __expf(e0 - M0h) * R0h;
            float t1 = g_as2[src * 8 + h1] + ad1v;
            float e1 = t1 > 0.f ? t1 : NEG_SLOPE * t1;
            s_w[lane * 8 + h1] = msk * __expf(e1 - M1h) * R1h;
        }
        for (int i = tid; i < cnt * 16; i += 128) {
            int r = i >> 4, q = i & 15;
            int src = (int)(g_csr[row + base + r] & 0x7fffffffu);
            ((float4*)s_rows[r])[q] = ((const float4*)(g_h1a + (size_t)src * 64))[q];
        }
        __syncthreads();
        for (int j = 0; j < cnt; j++) {
            float w = s_w[j * 8 + ht];
            float4 v = *(const float4*)&s_rows[j][ko];
            acc.x = fmaf(v.x, w, acc.x);
            acc.y = fmaf(v.y, w, acc.y);
            acc.z = fmaf(v.z, w, acc.z);
            acc.w = fmaf(v.w, w, acc.w);
        }
    }
    *(float4*)(g_agg + (size_t)n * 512 + tid * 4) = acc;
}

__global__ void k_out2(const float* __restrict__ W2, const float* __restrict__ b2, int N) {
    __shared__ __align__(16) float As[32][64];
    int tid = threadIdx.x;
    int hg = blockIdx.y;
    int row0 = blockIdx.x * 32;
    for (int i = tid; i < 32 * 16; i += 128) {
        int r = i >> 4, q = i & 15;
        int rr = min(row0 + r, N - 1);
        ((float4*)As[r])[q] = ((const float4*)(g_agg + (size_t)rr * 512 + hg * 64))[q];
    }
    __syncthreads();
    int col = hg * 128 + tid;
    float acc[32];
    #pragma unroll
    for (int r = 0; r < 32; r++) acc[r] = 0.f;
    #pragma unroll 4
    for (int k = 0; k < 64; k++) {
        float w = W2[(size_t)k * 1024 + col];
        #pragma unroll
        for (int r = 0; r < 32; r++) acc[r] = fmaf(As[r][k], w, acc[r]);
    }
    float bb = b2[col];
    #pragma unroll
    for (int r = 0; r < 32; r++) {
        int rr = row0 + r;
        if (rr < N) g_h2[(size_t)rr * 1024 + col] = acc[r] + bb;
    }
}

__global__ void k_lsm(float* __restrict__ out, int N) {
    __shared__ float red[256];
    int n = blockIdx.x, tid = threadIdx.x;
    float4 x = *(const float4*)(g_h2 + (size_t)n * 1024 + tid * 4);
    float tm = fmaxf(fmaxf(x.x, x.y), fmaxf(x.z, x.w));
    red[tid] = tm;
    __syncthreads();
    for (int s = 128; s > 0; s >>= 1) {
        if (tid < s) red[tid] = fmaxf(red[tid], red[tid + s]);
        __syncthreads();
    }
    float bmax = red[0];
    __syncthreads();
    float te = __expf(x.x - bmax) + __expf(x.y - bmax) + __expf(x.z - bmax) + __expf(x.w - bmax);
    red[tid] = te;
    __syncthreads();
    for (int s = 128; s > 0; s >>= 1) {
        if (tid < s) red[tid] += red[tid + s];
        __syncthreads();
    }
    float lse = bmax + logf(red[0]);
    float4 o = make_float4(x.x - lse, x.y - lse, x.z - lse, x.w - lse);
    *(float4*)(out + (size_t)n * 1024 + tid * 4) = o;
}

// ---------------- launcher (forked streams inside the capture) ----------------
extern "C" void kernel_launch(void* const* d_in, const int* in_sizes, int n_in,
                              void* d_out, int out_size) {
    const float* x   = (const float*)d_in[0];
    const int*   ei  = (const int*)d_in[1];
    const float* W1  = (const float*)d_in[2];
    const float* aS1 = (const float*)d_in[3];
    const float* aD1 = (const float*)d_in[4];
    const float* b1  = (const float*)d_in[5];
    const float* W2  = (const float*)d_in[6];
    const float* aS2 = (const float*)d_in[7];
    const float* aD2 = (const float*)d_in[8];
    const float* b2  = (const float*)d_in[9];
    float*       out = (float*)d_out;

    int N = in_sizes[0] / 128;
    int E = in_sizes[1] / 2;

    static cudaStream_t sB = nullptr;
    static cudaEvent_t evF = nullptr, evB = nullptr;
    static void* p_deg = nullptr;
    if (!sB) {
        cudaStreamCreateWithFlags(&sB, cudaStreamNonBlocking);
        cudaEventCreateWithFlags(&evF, cudaEventDisableTiming);
        cudaEventCreateWithFlags(&evB, cudaEventDisableTiming);
        cudaGetSymbolAddress(&p_deg, g_deg);
    }

    // fork: GEMM1(+attn1) and prep2 run concurrently with CSR build
    cudaEventRecord(evF, 0);
    cudaStreamWaitEvent(sB, evF, 0);
    k_gemm1f<<<(N + 15) / 16, 256, 0, sB>>>(x, W1, aS1, aD1, N);
    k_prep2 <<<1, 512, 0, sB>>>(W2, aS2, aD2);
    cudaEventRecord(evB, sB);

    cudaMemsetAsync(p_deg, 0, N * sizeof(int), 0);
    k_count<<<(E + 255) / 256, 256>>>(ei, E, N);
    k_scan <<<1, 1024>>>(N);
    k_fill <<<(E + 255) / 256, 256>>>(ei, E, N);

    // join
    cudaStreamWaitEvent(0, evB, 0);
    k_agg1f<<<(N * 32 + 255) / 256, 256>>>(b1, N);
    k_agg2 <<<N, 128>>>(N);
    dim3 g2((N + 31) / 32, 8);
    k_out2 <<<g2, 128>>>(W2, b2, N);
    k_lsm  <<<N, 256>>>(out, N);
}